// round 14
// baseline (speedup 1.0000x reference)
#include <cuda_runtime.h>
#include <cuda_bf16.h>
#include <math_constants.h>

// Problem constants
#define T_TOKENS 4096
#define HIDDEN   2048
#define N_EXP    8
#define H4       (HIDDEN / 4)          // 512 float4 per hidden row

// Output layout (floats), outputs concatenated:
//   [0, 32768)                router_scores [E, T]
//   [32768, +67108864)        router_indices [E*T, H] (value = t, as float)
//   [67141632, 67174400)      router_probs [E*T, 1] == scores flattened
#define SCORES_OFF 0
#define IDX_OFF    (N_EXP * T_TOKENS)                       // 32768
#define IDX_ELEMS  ((size_t)N_EXP * T_TOKENS * HIDDEN)      // 67108864
#define PROBS_OFF  (IDX_OFF + IDX_ELEMS)                    // 67141632
#define IDX_F4     (IDX_ELEMS / 4)                          // 16,777,216

// R8 structure with wave-quantization fix:
//   concurrency = 6 CTA/SM * 148 SM = 888; grid = 888*19 = 16872 exactly.
//   ids [0, 512)       logits blocks: 4 warps x 2 tokens (unchanged from R8)
//   ids [512, 16872)   fill blocks: balanced grid-stride over 16.7M float4
//                      (8-9 stores/thread; no near-empty 20th wave).
#define LOGITS_BLOCKS 512
#define TPW 2
#define FILL_BLOCKS 16360
#define GRID_BLOCKS (LOGITS_BLOCKS + FILL_BLOCKS)           // 16872 = 888*19
#define FILL_THREADS ((size_t)FILL_BLOCKS * 128)            // 2,094,080

__global__ __launch_bounds__(128, 6)
void router_fused_kernel(const float* __restrict__ hs,
                         const float* __restrict__ wr,
                         float* __restrict__ out) {
    const unsigned bid = blockIdx.x;

    if (bid >= LOGITS_BLOCKS) {
        // ---------------- fill branch: balanced grid-stride ----------------
        float4* __restrict__ out4 = (float4*)(out + IDX_OFF);
        const size_t tid = (size_t)(bid - LOGITS_BLOCKS) * 128 + threadIdx.x;
#pragma unroll 4
        for (size_t i = tid; i < IDX_F4; i += FILL_THREADS) {
            const float v = (float)((i >> 9) & (T_TOKENS - 1));
            __stcs(&out4[i], make_float4(v, v, v, v));
        }
        return;
    }

    // ------------------------- logits branch -------------------------
    const int warp = threadIdx.x >> 5;
    const int lane = threadIdx.x & 31;
    const int t0 = ((int)bid * 4 + warp) * TPW;      // 2 tokens per warp

    const float4* __restrict__ hs4 = (const float4*)hs;
    const float4* __restrict__ w4  = (const float4*)wr;

    float acc[TPW][N_EXP];
#pragma unroll
    for (int a = 0; a < TPW; a++)
#pragma unroll
        for (int e = 0; e < N_EXP; e++) acc[a][e] = 0.f;

#pragma unroll 2
    for (int ii = 0; ii < H4 / 32; ii++) {           // 16 iterations
        const int i = ii * 32 + lane;
        float4 x[TPW];
#pragma unroll
        for (int a = 0; a < TPW; a++)
            x[a] = hs4[(size_t)(t0 + a) * H4 + i];
#pragma unroll
        for (int e = 0; e < N_EXP; e++) {
            const float4 wv = __ldg(&w4[e * H4 + i]);
#pragma unroll
            for (int a = 0; a < TPW; a++) {
                acc[a][e] += x[a].x * wv.x + x[a].y * wv.y
                           + x[a].z * wv.z + x[a].w * wv.w;
            }
        }
    }

    // butterfly warp reduction
#pragma unroll
    for (int a = 0; a < TPW; a++)
#pragma unroll
        for (int e = 0; e < N_EXP; e++)
#pragma unroll
            for (int o = 16; o > 0; o >>= 1)
                acc[a][e] += __shfl_xor_sync(0xffffffffu, acc[a][e], o);

    if (lane == 0) {
#pragma unroll
        for (int a = 0; a < TPW; a++) {
            const int t = t0 + a;
            float b1 = -CUDART_INF_F; int i1 = 0;
#pragma unroll
            for (int e = 0; e < N_EXP; e++)
                if (acc[a][e] > b1) { b1 = acc[a][e]; i1 = e; }
            float b2 = -CUDART_INF_F; int i2 = -1;
#pragma unroll
            for (int e = 0; e < N_EXP; e++)
                if (e != i1 && acc[a][e] > b2) { b2 = acc[a][e]; i2 = e; }

            const float s1 = 1.f / (1.f + __expf(-b1));
            const float s2 = 1.f / (1.f + __expf(-b2));
#pragma unroll
            for (int e = 0; e < N_EXP; e++) {
                const float s = (e == i1) ? s1 : ((e == i2) ? s2 : 0.f);
                out[SCORES_OFF + (size_t)e * T_TOKENS + t] = s;
                out[PROBS_OFF  + (size_t)e * T_TOKENS + t] = s;
            }
        }
    }
}

extern "C" void kernel_launch(void* const* d_in, const int* in_sizes, int n_in,
                              void* d_out, int out_size) {
    const float* hs = (const float*)d_in[0];  // [T, H] fp32
    const float* wr = (const float*)d_in[1];  // [E, H] fp32
    float* out = (float*)d_out;

    router_fused_kernel<<<GRID_BLOCKS, 128>>>(hs, wr, out);
}

// round 15
// speedup vs baseline: 1.0287x; 1.0287x over previous
#include <cuda_runtime.h>
#include <cuda_bf16.h>
#include <math_constants.h>

// Problem constants
#define T_TOKENS 4096
#define HIDDEN   2048
#define N_EXP    8
#define H4       (HIDDEN / 4)          // 512 float4 per hidden row

// Output layout (floats), outputs concatenated:
//   [0, 32768)                router_scores [E, T]
//   [32768, +67108864)        router_indices [E*T, H] (value = t, as float)
//   [67141632, 67174400)      router_probs [E*T, 1] == scores flattened
#define SCORES_OFF 0
#define IDX_OFF    (N_EXP * T_TOKENS)                       // 32768
#define IDX_ELEMS  ((size_t)N_EXP * T_TOKENS * HIDDEN)      // 67108864
#define IDX_F4     (IDX_ELEMS / 4)                          // 16,777,216
#define PROBS_OFF  (IDX_OFF + IDX_ELEMS)                    // 67141632

// Balanced-wave grid (888 concurrent CTAs * 19 = 16872) with STATIC fill
// indexing (R14's grid-stride bound checks doubled ALU/issue -> regressed):
//   ids [0, 512)       logits blocks (R8 config, unchanged)
//   ids [512, 16872)   fill blocks: 1024 f4 region each (8 stores/thread);
//                      first EXTRA_BLOCKS fill blocks do 1 extra store to
//                      cover the remainder 16777216 - 16360*1024 = 24576 f4.
#define LOGITS_BLOCKS 512
#define TPW 2
#define FILL_BLOCKS 16360
#define GRID_BLOCKS (LOGITS_BLOCKS + FILL_BLOCKS)           // 16872 = 888*19
#define FILL_F4_PER_BLOCK 1024
#define MAIN_F4 ((size_t)FILL_BLOCKS * FILL_F4_PER_BLOCK)   // 16,752,640
#define EXTRA_F4 (IDX_F4 - MAIN_F4)                         // 24,576
#define EXTRA_BLOCKS (EXTRA_F4 / 128)                       // 192

__global__ __launch_bounds__(128, 6)
void router_fused_kernel(const float* __restrict__ hs,
                         const float* __restrict__ wr,
                         float* __restrict__ out) {
    const unsigned bid = blockIdx.x;

    if (bid >= LOGITS_BLOCKS) {
        // ------------------ fill branch: static indexing ------------------
        const unsigned fid = bid - LOGITS_BLOCKS;      // 0 .. 16359
        float4* __restrict__ out4 = (float4*)(out + IDX_OFF);
        const size_t base = (size_t)fid * FILL_F4_PER_BLOCK + threadIdx.x;
#pragma unroll
        for (int j = 0; j < 8; j++) {
            const size_t i = base + (size_t)j * 128;
            const float v = (float)((i >> 9) & (T_TOKENS - 1));
            __stcs(&out4[i], make_float4(v, v, v, v));
        }
        // remainder: first 192 fill blocks store one extra float4 each
        if (fid < EXTRA_BLOCKS) {
            const size_t i = MAIN_F4 + (size_t)fid * 128 + threadIdx.x;
            const float v = (float)((i >> 9) & (T_TOKENS - 1));
            __stcs(&out4[i], make_float4(v, v, v, v));
        }
        return;
    }

    // ------------------------- logits branch -------------------------
    const int warp = threadIdx.x >> 5;
    const int lane = threadIdx.x & 31;
    const int t0 = ((int)bid * 4 + warp) * TPW;      // 2 tokens per warp

    const float4* __restrict__ hs4 = (const float4*)hs;
    const float4* __restrict__ w4  = (const float4*)wr;

    float acc[TPW][N_EXP];
#pragma unroll
    for (int a = 0; a < TPW; a++)
#pragma unroll
        for (int e = 0; e < N_EXP; e++) acc[a][e] = 0.f;

#pragma unroll 2
    for (int ii = 0; ii < H4 / 32; ii++) {           // 16 iterations
        const int i = ii * 32 + lane;
        float4 x[TPW];
#pragma unroll
        for (int a = 0; a < TPW; a++)
            x[a] = hs4[(size_t)(t0 + a) * H4 + i];
#pragma unroll
        for (int e = 0; e < N_EXP; e++) {
            const float4 wv = __ldg(&w4[e * H4 + i]);
#pragma unroll
            for (int a = 0; a < TPW; a++) {
                acc[a][e] += x[a].x * wv.x + x[a].y * wv.y
                           + x[a].z * wv.z + x[a].w * wv.w;
            }
        }
    }

    // butterfly warp reduction
#pragma unroll
    for (int a = 0; a < TPW; a++)
#pragma unroll
        for (int e = 0; e < N_EXP; e++)
#pragma unroll
            for (int o = 16; o > 0; o >>= 1)
                acc[a][e] += __shfl_xor_sync(0xffffffffu, acc[a][e], o);

    if (lane == 0) {
#pragma unroll
        for (int a = 0; a < TPW; a++) {
            const int t = t0 + a;
            float b1 = -CUDART_INF_F; int i1 = 0;
#pragma unroll
            for (int e = 0; e < N_EXP; e++)
                if (acc[a][e] > b1) { b1 = acc[a][e]; i1 = e; }
            float b2 = -CUDART_INF_F; int i2 = -1;
#pragma unroll
            for (int e = 0; e < N_EXP; e++)
                if (e != i1 && acc[a][e] > b2) { b2 = acc[a][e]; i2 = e; }

            const float s1 = 1.f / (1.f + __expf(-b1));
            const float s2 = 1.f / (1.f + __expf(-b2));
#pragma unroll
            for (int e = 0; e < N_EXP; e++) {
                const float s = (e == i1) ? s1 : ((e == i2) ? s2 : 0.f);
                out[SCORES_OFF + (size_t)e * T_TOKENS + t] = s;
                out[PROBS_OFF  + (size_t)e * T_TOKENS + t] = s;
            }
        }
    }
}

extern "C" void kernel_launch(void* const* d_in, const int* in_sizes, int n_in,
                              void* d_out, int out_size) {
    const float* hs = (const float*)d_in[0];  // [T, H] fp32
    const float* wr = (const float*)d_in[1];  // [E, H] fp32
    float* out = (float*)d_out;

    router_fused_kernel<<<GRID_BLOCKS, 128>>>(hs, wr, out);
}